// round 1
// baseline (speedup 1.0000x reference)
#include <cuda_runtime.h>
#include <cstdint>

#define H      512
#define EPB    8      // edges per block (1 warp each)

// ---------------- f32x2 helpers (Blackwell packed fp32 FMA) ----------------
__device__ __forceinline__ unsigned long long pack2(float x, float y) {
    unsigned long long r;
    asm("mov.b64 %0, {%1, %2};" : "=l"(r) : "f"(x), "f"(y));
    return r;
}
__device__ __forceinline__ void unpack2(unsigned long long v, float& x, float& y) {
    asm("mov.b64 {%0, %1}, %2;" : "=f"(x), "=f"(y) : "l"(v));
}
__device__ __forceinline__ void ffma2(unsigned long long& c, unsigned long long a,
                                      unsigned long long b) {
    asm("fma.rn.f32x2 %0, %1, %2, %0;" : "+l"(c) : "l"(a), "l"(b));
}
__device__ __forceinline__ void red4(float* p, float4 v) {
    asm volatile("red.global.add.v4.f32 [%0], {%1, %2, %3, %4};"
                 :: "l"(p), "f"(v.x), "f"(v.y), "f"(v.z), "f"(v.w) : "memory");
}

// ---------------- GEMM: C = emb @ W + bias (write-only C) ----------------
// BM=128, BN=128, BK=8, 256 threads, each thread computes 8x8 via f32x2 pairs.
#define BM 128
#define BN 128
#define BK 8
#define TM 8
#define TN 8

__global__ __launch_bounds__(256, 2)
void gemm_bias_kernel(const float* __restrict__ A, const float* __restrict__ W,
                      const float* __restrict__ bias, float* __restrict__ C, int M)
{
    __shared__ __align__(16) float As[BK][BM];   // A^T tile
    __shared__ __align__(16) float Bs[BK][BN];

    const int bn  = blockIdx.x * BN;
    const int bm  = blockIdx.y * BM;
    const int tid = threadIdx.x;
    const int tx  = tid & 15;    // column-tile index
    const int ty  = tid >> 4;    // row-tile index

    unsigned long long acc[TM][TN / 2];
#pragma unroll
    for (int i = 0; i < TM; i++)
#pragma unroll
        for (int j = 0; j < TN / 2; j++) acc[i][j] = pack2(0.f, 0.f);

    // Global-load mapping
    const int a_row = tid >> 1;          // 0..127
    const int a_kq  = tid & 1;           // which float4 along k
    const int b_k   = tid >> 5;          // 0..7
    const int b_n4  = (tid & 31) * 4;    // 0..124

    for (int kt = 0; kt < H; kt += BK) {
        // --- load A tile (transposed into smem), guard tail rows ---
        float4 av = make_float4(0.f, 0.f, 0.f, 0.f);
        const int grow = bm + a_row;
        if (grow < M)
            av = *(const float4*)(A + (size_t)grow * H + kt + a_kq * 4);
        As[a_kq * 4 + 0][a_row] = av.x;
        As[a_kq * 4 + 1][a_row] = av.y;
        As[a_kq * 4 + 2][a_row] = av.z;
        As[a_kq * 4 + 3][a_row] = av.w;
        // --- load B tile ---
        float4 bv = *(const float4*)(W + (size_t)(kt + b_k) * H + bn + b_n4);
        *(float4*)&Bs[b_k][b_n4] = bv;
        __syncthreads();

#pragma unroll
        for (int k = 0; k < BK; k++) {
            float4 a0 = *(const float4*)&As[k][ty * TM + 0];
            float4 a1 = *(const float4*)&As[k][ty * TM + 4];
            float4 b0 = *(const float4*)&Bs[k][tx * TN + 0];
            float4 b1 = *(const float4*)&Bs[k][tx * TN + 4];
            unsigned long long bp[4] = { pack2(b0.x, b0.y), pack2(b0.z, b0.w),
                                         pack2(b1.x, b1.y), pack2(b1.z, b1.w) };
            float am[TM] = { a0.x, a0.y, a0.z, a0.w, a1.x, a1.y, a1.z, a1.w };
#pragma unroll
            for (int i = 0; i < TM; i++) {
                unsigned long long ad = pack2(am[i], am[i]);
#pragma unroll
                for (int j = 0; j < 4; j++) ffma2(acc[i][j], ad, bp[j]);
            }
        }
        __syncthreads();
    }

    // --- epilogue: add bias, store (write-only; edge kernel atomics come after) ---
    float bvals[TN];
#pragma unroll
    for (int j = 0; j < TN; j++) bvals[j] = bias[bn + tx * TN + j];

#pragma unroll
    for (int i = 0; i < TM; i++) {
        const int grow = bm + ty * TM + i;
        if (grow < M) {
            float o[TN];
#pragma unroll
            for (int j = 0; j < 4; j++) {
                float lo, hi;
                unpack2(acc[i][j], lo, hi);
                o[2 * j]     = lo + bvals[2 * j];
                o[2 * j + 1] = hi + bvals[2 * j + 1];
            }
            float4* dst = (float4*)(C + (size_t)grow * H + bn + tx * TN);
            dst[0] = make_float4(o[0], o[1], o[2], o[3]);
            dst[1] = make_float4(o[4], o[5], o[6], o[7]);
        }
    }
}

// ---------------- Edge kernel: block-diagonal matvec + norm + scatter ----------------
// One warp per edge. Lane l owns bases 4l..4l+3 (h[16l..16l+15], out[16l..16l+15]).
__global__ __launch_bounds__(256)
void edge_kernel(const void* __restrict__ srcv, const void* __restrict__ dstv,
                 const void* __restrict__ etv, const float* __restrict__ norm,
                 const float* __restrict__ emb, const float* __restrict__ wt,
                 float* __restrict__ out, int E)
{
    __shared__ int is64;
    if (threadIdx.x == 0) {
        // dtype sniff: int64 values < 2^31 have all-zero odd 32-bit words
        const int* s = (const int*)srcv;
        int orv = 0;
#pragma unroll
        for (int j = 0; j < 32; j++) orv |= s[2 * j + 1];
        is64 = (orv == 0) ? 1 : 0;
    }
    __syncthreads();

    const int warp = threadIdx.x >> 5;
    const int lane = threadIdx.x & 31;
    const int e    = blockIdx.x * EPB + warp;
    if (e >= E) return;

    long long s, d, t;
    if (is64) {
        s = ((const long long*)srcv)[e];
        d = ((const long long*)dstv)[e];
        t = ((const long long*)etv)[e];
    } else {
        s = ((const int*)srcv)[e];
        d = ((const int*)dstv)[e];
        t = ((const int*)etv)[e];
    }
    const float nr = norm[e];

    const float4* h4 = (const float4*)(emb + (size_t)s * H) + lane * 4;
    const float4* w4 = (const float4*)(wt + (size_t)t * 2048) + lane * 16;
    float* obase     = out + (size_t)d * H + lane * 16;

    float4 hv[4];
#pragma unroll
    for (int jb = 0; jb < 4; jb++) hv[jb] = h4[jb];

#pragma unroll
    for (int jb = 0; jb < 4; jb++) {
        const float4 w0 = w4[jb * 4 + 0];
        const float4 w1 = w4[jb * 4 + 1];
        const float4 w2 = w4[jb * 4 + 2];
        const float4 w3 = w4[jb * 4 + 3];
        const float4 h  = hv[jb];
        float4 m;
        m.x = fmaf(h.w, w3.x, fmaf(h.z, w2.x, fmaf(h.y, w1.x, h.x * w0.x)));
        m.y = fmaf(h.w, w3.y, fmaf(h.z, w2.y, fmaf(h.y, w1.y, h.x * w0.y)));
        m.z = fmaf(h.w, w3.z, fmaf(h.z, w2.z, fmaf(h.y, w1.z, h.x * w0.z)));
        m.w = fmaf(h.w, w3.w, fmaf(h.z, w2.w, fmaf(h.y, w1.w, h.x * w0.w)));
        m.x *= nr; m.y *= nr; m.z *= nr; m.w *= nr;
        red4(obase + jb * 4, m);
    }
}

// ---------------- launch ----------------
extern "C" void kernel_launch(void* const* d_in, const int* in_sizes, int n_in,
                              void* d_out, int out_size)
{
    // inputs: 0=node_ids (arange -> identity, unused), 1=src, 2=dst, 3=etypes,
    //         4=norm, 5=emb, 6=weight, 7=loop_weight, 8=bias
    const float* norm = (const float*)d_in[4];
    const float* emb  = (const float*)d_in[5];
    const float* wt   = (const float*)d_in[6];
    const float* lw   = (const float*)d_in[7];
    const float* bias = (const float*)d_in[8];
    float* out = (float*)d_out;

    const int M = in_sizes[5] / H;   // 100000 nodes
    const int E = in_sizes[1];       // 150000 edges

    // 1) out = emb @ loop_weight + bias  (write-only, covers every element)
    dim3 grid(H / BN, (M + BM - 1) / BM);
    gemm_bias_kernel<<<grid, 256>>>(emb, lw, bias, out, M);

    // 2) out[dst] += norm * blockdiag(weight[etype]) @ emb[src]
    edge_kernel<<<(E + EPB - 1) / EPB, 256>>>(d_in[1], d_in[2], d_in[3],
                                              norm, emb, wt, out, E);
}

// round 3
// speedup vs baseline: 1.6200x; 1.6200x over previous
#include <cuda_runtime.h>
#include <cstdint>

#define H      512
#define EPB    8

// ---------------- scratch: transposed loop weight, tf32-rounded ----------------
__device__ unsigned int g_Bt[H * H];   // Bt[n][k] = tf32(lw[k][n]) bit pattern

__device__ __forceinline__ unsigned int f2tf32(float f) {
    unsigned int u;
    asm("cvt.rna.tf32.f32 %0, %1;" : "=r"(u) : "f"(f));
    return u;
}
__device__ __forceinline__ void red4(float* p, float4 v) {
    asm volatile("red.global.add.v4.f32 [%0], {%1, %2, %3, %4};"
                 :: "l"(p), "f"(v.x), "f"(v.y), "f"(v.z), "f"(v.w) : "memory");
}

// ---------------- transpose 512x512 + tf32 round ----------------
__global__ void transpose512(const float* __restrict__ lw) {
    __shared__ float t[32][33];
    const int bx = blockIdx.x * 32, by = blockIdx.y * 32;
#pragma unroll
    for (int j = 0; j < 4; j++)
        t[threadIdx.y + 8 * j][threadIdx.x] =
            lw[(by + threadIdx.y + 8 * j) * H + bx + threadIdx.x];
    __syncthreads();
#pragma unroll
    for (int j = 0; j < 4; j++)
        g_Bt[(bx + threadIdx.y + 8 * j) * H + by + threadIdx.x] =
            f2tf32(t[threadIdx.x][threadIdx.y + 8 * j]);
}

// ---------------- mma.sync tf32 GEMM: out = emb @ lw + bias ----------------
// BM=128, BN=128, BK=16, 256 threads. Warp grid 4(M)x2(N): warp tile 32x64.
// Smem stride 20 floats -> conflict-free fragment loads.
#define BK     16
#define LDS_S  20
#define BUFSZ  (128 * LDS_S)       // floats per operand buffer

__global__ __launch_bounds__(256, 1)
void gemm_mma_kernel(const float* __restrict__ A, const float* __restrict__ bias,
                     float* __restrict__ C, int M)
{
    __shared__ unsigned int As[2][BUFSZ];
    __shared__ unsigned int Bs[2][BUFSZ];

    const int tid  = threadIdx.x;
    const int wid  = tid >> 5;
    const int lane = tid & 31;
    const int l4   = lane >> 2;     // 0..7
    const int lm   = lane & 3;      // 0..3
    const int bm   = blockIdx.x * 128;
    const int bn   = blockIdx.y * 128;
    const int wm0  = (wid & 3) * 32;    // warp M offset in tile
    const int wn0  = (wid >> 2) * 64;   // warp N offset in tile

    float acc[2][8][4];
#pragma unroll
    for (int i = 0; i < 2; i++)
#pragma unroll
        for (int j = 0; j < 8; j++)
#pragma unroll
            for (int q = 0; q < 4; q++) acc[i][j][q] = 0.f;

    // global-load mapping: 512 float4 per operand tile, 2 per thread
    // f4idx = tid + i*256 ; row = f4idx>>2, kq = f4idx&3
    float4 stA[2], stB[2];

    auto load_regs = [&](int kt) {
#pragma unroll
        for (int i = 0; i < 2; i++) {
            const int f4 = tid + i * 256;
            const int row = f4 >> 2, kq = f4 & 3;
            const int gm = bm + row;
            stA[i] = make_float4(0.f, 0.f, 0.f, 0.f);
            if (gm < M) stA[i] = *(const float4*)(A + (size_t)gm * H + kt + kq * 4);
            stB[i] = *(const float4*)((const float*)g_Bt + (size_t)(bn + row) * H + kt + kq * 4);
        }
    };
    auto store_smem = [&](int b) {
#pragma unroll
        for (int i = 0; i < 2; i++) {
            const int f4 = tid + i * 256;
            const int row = f4 >> 2, kq = f4 & 3;
            uint4 av;
            av.x = f2tf32(stA[i].x); av.y = f2tf32(stA[i].y);
            av.z = f2tf32(stA[i].z); av.w = f2tf32(stA[i].w);
            *(uint4*)&As[b][row * LDS_S + kq * 4] = av;
            uint4 bv;   // already tf32 bits
            bv.x = __float_as_uint(stB[i].x); bv.y = __float_as_uint(stB[i].y);
            bv.z = __float_as_uint(stB[i].z); bv.w = __float_as_uint(stB[i].w);
            *(uint4*)&Bs[b][row * LDS_S + kq * 4] = bv;
        }
    };

    load_regs(0);
    store_smem(0);
    __syncthreads();

    const int NK = H / BK;   // 32
    for (int kt = 0; kt < NK; kt++) {
        if (kt + 1 < NK) load_regs((kt + 1) * BK);

        const int b = kt & 1;
#pragma unroll
        for (int ks = 0; ks < 2; ks++) {
            const int k8 = ks * 8;
            unsigned int af[2][4];
#pragma unroll
            for (int mt = 0; mt < 2; mt++) {
                const int rm = wm0 + mt * 16 + l4;
                af[mt][0] = As[b][rm * LDS_S + k8 + lm];
                af[mt][1] = As[b][(rm + 8) * LDS_S + k8 + lm];
                af[mt][2] = As[b][rm * LDS_S + k8 + lm + 4];
                af[mt][3] = As[b][(rm + 8) * LDS_S + k8 + lm + 4];
            }
#pragma unroll
            for (int nt = 0; nt < 8; nt++) {
                const int cn = wn0 + nt * 8 + l4;
                const unsigned int b0 = Bs[b][cn * LDS_S + k8 + lm];
                const unsigned int b1 = Bs[b][cn * LDS_S + k8 + lm + 4];
#pragma unroll
                for (int mt = 0; mt < 2; mt++) {
                    asm volatile(
                        "mma.sync.aligned.m16n8k8.row.col.f32.tf32.tf32.f32 "
                        "{%0,%1,%2,%3}, {%4,%5,%6,%7}, {%8,%9}, {%0,%1,%2,%3};"
                        : "+f"(acc[mt][nt][0]), "+f"(acc[mt][nt][1]),
                          "+f"(acc[mt][nt][2]), "+f"(acc[mt][nt][3])
                        : "r"(af[mt][0]), "r"(af[mt][1]), "r"(af[mt][2]), "r"(af[mt][3]),
                          "r"(b0), "r"(b1));
                }
            }
        }

        if (kt + 1 < NK) store_smem((kt + 1) & 1);
        __syncthreads();
    }

    // ---- epilogue: bias + store ----
#pragma unroll
    for (int mt = 0; mt < 2; mt++) {
        const int r0 = bm + wm0 + mt * 16 + l4;
        const int r1 = r0 + 8;
#pragma unroll
        for (int nt = 0; nt < 8; nt++) {
            const int c = bn + wn0 + nt * 8 + lm * 2;
            const float b0 = bias[c], b1 = bias[c + 1];
            if (r0 < M) {
                float2 v = make_float2(acc[mt][nt][0] + b0, acc[mt][nt][1] + b1);
                *(float2*)(C + (size_t)r0 * H + c) = v;
            }
            if (r1 < M) {
                float2 v = make_float2(acc[mt][nt][2] + b0, acc[mt][nt][3] + b1);
                *(float2*)(C + (size_t)r1 * H + c) = v;
            }
        }
    }
}

// ---------------- Edge kernel (unchanged) ----------------
__global__ __launch_bounds__(256)
void edge_kernel(const void* __restrict__ srcv, const void* __restrict__ dstv,
                 const void* __restrict__ etv, const float* __restrict__ norm,
                 const float* __restrict__ emb, const float* __restrict__ wt,
                 float* __restrict__ out, int E)
{
    __shared__ int is64;
    if (threadIdx.x == 0) {
        const int* s = (const int*)srcv;
        int orv = 0;
#pragma unroll
        for (int j = 0; j < 32; j++) orv |= s[2 * j + 1];
        is64 = (orv == 0) ? 1 : 0;
    }
    __syncthreads();

    const int warp = threadIdx.x >> 5;
    const int lane = threadIdx.x & 31;
    const int e    = blockIdx.x * EPB + warp;
    if (e >= E) return;

    long long s, d, t;
    if (is64) {
        s = ((const long long*)srcv)[e];
        d = ((const long long*)dstv)[e];
        t = ((const long long*)etv)[e];
    } else {
        s = ((const int*)srcv)[e];
        d = ((const int*)dstv)[e];
        t = ((const int*)etv)[e];
    }
    const float nr = norm[e];

    const float4* h4 = (const float4*)(emb + (size_t)s * H) + lane * 4;
    const float4* w4 = (const float4*)(wt + (size_t)t * 2048) + lane * 16;
    float* obase     = out + (size_t)d * H + lane * 16;

    float4 hv[4];
#pragma unroll
    for (int jb = 0; jb < 4; jb++) hv[jb] = h4[jb];

#pragma unroll
    for (int jb = 0; jb < 4; jb++) {
        const float4 w0 = w4[jb * 4 + 0];
        const float4 w1 = w4[jb * 4 + 1];
        const float4 w2 = w4[jb * 4 + 2];
        const float4 w3 = w4[jb * 4 + 3];
        const float4 h  = hv[jb];
        float4 m;
        m.x = fmaf(h.w, w3.x, fmaf(h.z, w2.x, fmaf(h.y, w1.x, h.x * w0.x)));
        m.y = fmaf(h.w, w3.y, fmaf(h.z, w2.y, fmaf(h.y, w1.y, h.x * w0.y)));
        m.z = fmaf(h.w, w3.z, fmaf(h.z, w2.z, fmaf(h.y, w1.z, h.x * w0.z)));
        m.w = fmaf(h.w, w3.w, fmaf(h.z, w2.w, fmaf(h.y, w1.w, h.x * w0.w)));
        m.x *= nr; m.y *= nr; m.z *= nr; m.w *= nr;
        red4(obase + jb * 4, m);
    }
}

// ---------------- launch ----------------
extern "C" void kernel_launch(void* const* d_in, const int* in_sizes, int n_in,
                              void* d_out, int out_size)
{
    // 0=node_ids (arange, unused), 1=src, 2=dst, 3=etypes, 4=norm,
    // 5=emb, 6=weight, 7=loop_weight, 8=bias
    const float* norm = (const float*)d_in[4];
    const float* emb  = (const float*)d_in[5];
    const float* wt   = (const float*)d_in[6];
    const float* lw   = (const float*)d_in[7];
    const float* bias = (const float*)d_in[8];
    float* out = (float*)d_out;

    const int M = in_sizes[5] / H;
    const int E = in_sizes[1];

    transpose512<<<dim3(16, 16), dim3(32, 8)>>>(lw);

    dim3 grid((M + 127) / 128, H / 128);
    gemm_mma_kernel<<<grid, 256>>>(emb, bias, out, M);

    edge_kernel<<<(E + EPB - 1) / EPB, 256>>>(d_in[1], d_in[2], d_in[3],
                                              norm, emb, wt, out, E);
}

// round 4
// speedup vs baseline: 1.7869x; 1.1030x over previous
#include <cuda_runtime.h>
#include <cstdint>

#define H      512
#define EPB    8

// ---------------- scratch: transposed loop weight, tf32-rounded ----------------
__device__ unsigned int g_Bt[H * H];   // Bt[n][k] = tf32(lw[k][n]) bit pattern

__device__ __forceinline__ unsigned int f2tf32(float f) {
    unsigned int u;
    asm("cvt.rna.tf32.f32 %0, %1;" : "=r"(u) : "f"(f));
    return u;
}
__device__ __forceinline__ void red4(float* p, float4 v) {
    asm volatile("red.global.add.v4.f32 [%0], {%1, %2, %3, %4};"
                 :: "l"(p), "f"(v.x), "f"(v.y), "f"(v.z), "f"(v.w) : "memory");
}
__device__ __forceinline__ void red2(float* p, float a, float b) {
    asm volatile("red.global.add.v2.f32 [%0], {%1, %2};"
                 :: "l"(p), "f"(a), "f"(b) : "memory");
}

// ---------------- transpose 512x512 + tf32 round ----------------
__global__ void transpose512(const float* __restrict__ lw) {
    __shared__ float t[32][33];
    const int bx = blockIdx.x * 32, by = blockIdx.y * 32;
#pragma unroll
    for (int j = 0; j < 4; j++)
        t[threadIdx.y + 8 * j][threadIdx.x] =
            lw[(by + threadIdx.y + 8 * j) * H + bx + threadIdx.x];
    __syncthreads();
#pragma unroll
    for (int j = 0; j < 4; j++)
        g_Bt[(bx + threadIdx.y + 8 * j) * H + by + threadIdx.x] =
            f2tf32(t[threadIdx.x][threadIdx.y + 8 * j]);
}

// ---------------- fused kernel: heterogeneous grid ----------------
// Blocks [0, GB): tf32 mma GEMM tile (128x128), epilogue red.add (+bias).
// Blocks [GB, GB+EB): edge message blocks (8 warps, 1 edge each).
// out must be pre-zeroed (cudaMemsetAsync).
#define BK     16
#define LDS_S  20
#define BUFSZ  (128 * LDS_S)

__global__ __launch_bounds__(256)
void fused_kernel(const float* __restrict__ A, const float* __restrict__ bias,
                  const void* __restrict__ srcv, const void* __restrict__ dstv,
                  const void* __restrict__ etv, const float* __restrict__ norm,
                  const float* __restrict__ wt,
                  float* __restrict__ out, int M, int E, int GB)
{
    const int tid  = threadIdx.x;
    const int wid  = tid >> 5;
    const int lane = tid & 31;

    if (blockIdx.x < GB) {
        // ================= GEMM part =================
        __shared__ unsigned int As[2][BUFSZ];
        __shared__ unsigned int Bs[2][BUFSZ];

        const int l4  = lane >> 2;
        const int lm  = lane & 3;
        const int bm  = (blockIdx.x >> 2) * 128;
        const int bn  = (blockIdx.x & 3) * 128;
        const int wm0 = (wid & 3) * 32;
        const int wn0 = (wid >> 2) * 64;

        float acc[2][8][4];
#pragma unroll
        for (int i = 0; i < 2; i++)
#pragma unroll
            for (int j = 0; j < 8; j++)
#pragma unroll
                for (int q = 0; q < 4; q++) acc[i][j][q] = 0.f;

        float4 stA[2], stB[2];
        auto load_regs = [&](int kt) {
#pragma unroll
            for (int i = 0; i < 2; i++) {
                const int f4 = tid + i * 256;
                const int row = f4 >> 2, kq = f4 & 3;
                const int gm = bm + row;
                stA[i] = make_float4(0.f, 0.f, 0.f, 0.f);
                if (gm < M) stA[i] = *(const float4*)(A + (size_t)gm * H + kt + kq * 4);
                stB[i] = *(const float4*)((const float*)g_Bt + (size_t)(bn + row) * H + kt + kq * 4);
            }
        };
        auto store_smem = [&](int b) {
#pragma unroll
            for (int i = 0; i < 2; i++) {
                const int f4 = tid + i * 256;
                const int row = f4 >> 2, kq = f4 & 3;
                uint4 av;
                av.x = f2tf32(stA[i].x); av.y = f2tf32(stA[i].y);
                av.z = f2tf32(stA[i].z); av.w = f2tf32(stA[i].w);
                *(uint4*)&As[b][row * LDS_S + kq * 4] = av;
                uint4 bv;
                bv.x = __float_as_uint(stB[i].x); bv.y = __float_as_uint(stB[i].y);
                bv.z = __float_as_uint(stB[i].z); bv.w = __float_as_uint(stB[i].w);
                *(uint4*)&Bs[b][row * LDS_S + kq * 4] = bv;
            }
        };

        load_regs(0);
        store_smem(0);
        __syncthreads();

        const int NK = H / BK;
        for (int kt = 0; kt < NK; kt++) {
            if (kt + 1 < NK) load_regs((kt + 1) * BK);

            const int b = kt & 1;
#pragma unroll
            for (int ks = 0; ks < 2; ks++) {
                const int k8 = ks * 8;
                unsigned int af[2][4];
#pragma unroll
                for (int mt = 0; mt < 2; mt++) {
                    const int rm = wm0 + mt * 16 + l4;
                    af[mt][0] = As[b][rm * LDS_S + k8 + lm];
                    af[mt][1] = As[b][(rm + 8) * LDS_S + k8 + lm];
                    af[mt][2] = As[b][rm * LDS_S + k8 + lm + 4];
                    af[mt][3] = As[b][(rm + 8) * LDS_S + k8 + lm + 4];
                }
#pragma unroll
                for (int nt = 0; nt < 8; nt++) {
                    const int cn = wn0 + nt * 8 + l4;
                    const unsigned int b0 = Bs[b][cn * LDS_S + k8 + lm];
                    const unsigned int b1 = Bs[b][cn * LDS_S + k8 + lm + 4];
#pragma unroll
                    for (int mt = 0; mt < 2; mt++) {
                        asm volatile(
                            "mma.sync.aligned.m16n8k8.row.col.f32.tf32.tf32.f32 "
                            "{%0,%1,%2,%3}, {%4,%5,%6,%7}, {%8,%9}, {%0,%1,%2,%3};"
                            : "+f"(acc[mt][nt][0]), "+f"(acc[mt][nt][1]),
                              "+f"(acc[mt][nt][2]), "+f"(acc[mt][nt][3])
                            : "r"(af[mt][0]), "r"(af[mt][1]), "r"(af[mt][2]), "r"(af[mt][3]),
                              "r"(b0), "r"(b1));
                    }
                }
            }

            if (kt + 1 < NK) store_smem((kt + 1) & 1);
            __syncthreads();
        }

        // epilogue: atomic accumulate (out pre-zeroed; edge part may run concurrently)
#pragma unroll
        for (int mt = 0; mt < 2; mt++) {
            const int r0 = bm + wm0 + mt * 16 + l4;
            const int r1 = r0 + 8;
#pragma unroll
            for (int nt = 0; nt < 8; nt++) {
                const int c = bn + wn0 + nt * 8 + lm * 2;
                const float b0 = bias[c], b1 = bias[c + 1];
                if (r0 < M) red2(out + (size_t)r0 * H + c,
                                 acc[mt][nt][0] + b0, acc[mt][nt][1] + b1);
                if (r1 < M) red2(out + (size_t)r1 * H + c,
                                 acc[mt][nt][2] + b0, acc[mt][nt][3] + b1);
            }
        }
    } else {
        // ================= edge part =================
        __shared__ int is64;
        if (tid == 0) {
            const int* s = (const int*)srcv;
            int orv = 0;
#pragma unroll
            for (int j = 0; j < 32; j++) orv |= s[2 * j + 1];
            is64 = (orv == 0) ? 1 : 0;
        }
        __syncthreads();

        const int e = (blockIdx.x - GB) * EPB + wid;
        if (e >= E) return;

        long long s, d, t;
        if (is64) {
            s = ((const long long*)srcv)[e];
            d = ((const long long*)dstv)[e];
            t = ((const long long*)etv)[e];
        } else {
            s = ((const int*)srcv)[e];
            d = ((const int*)dstv)[e];
            t = ((const int*)etv)[e];
        }
        const float nr = norm[e];

        const float4* h4 = (const float4*)(A + (size_t)s * H) + lane * 4;
        const float4* w4 = (const float4*)(wt + (size_t)t * 2048) + lane * 16;
        float* obase     = out + (size_t)d * H + lane * 16;

        float4 hv[4];
#pragma unroll
        for (int jb = 0; jb < 4; jb++) hv[jb] = h4[jb];

#pragma unroll
        for (int jb = 0; jb < 4; jb++) {
            const float4 w0 = w4[jb * 4 + 0];
            const float4 w1 = w4[jb * 4 + 1];
            const float4 w2 = w4[jb * 4 + 2];
            const float4 w3 = w4[jb * 4 + 3];
            const float4 h  = hv[jb];
            float4 m;
            m.x = fmaf(h.w, w3.x, fmaf(h.z, w2.x, fmaf(h.y, w1.x, h.x * w0.x)));
            m.y = fmaf(h.w, w3.y, fmaf(h.z, w2.y, fmaf(h.y, w1.y, h.x * w0.y)));
            m.z = fmaf(h.w, w3.z, fmaf(h.z, w2.z, fmaf(h.y, w1.z, h.x * w0.z)));
            m.w = fmaf(h.w, w3.w, fmaf(h.z, w2.w, fmaf(h.y, w1.w, h.x * w0.w)));
            m.x *= nr; m.y *= nr; m.z *= nr; m.w *= nr;
            red4(obase + jb * 4, m);
        }
    }
}

// ---------------- launch ----------------
extern "C" void kernel_launch(void* const* d_in, const int* in_sizes, int n_in,
                              void* d_out, int out_size)
{
    // 0=node_ids (arange, unused), 1=src, 2=dst, 3=etypes, 4=norm,
    // 5=emb, 6=weight, 7=loop_weight, 8=bias
    const float* norm = (const float*)d_in[4];
    const float* emb  = (const float*)d_in[5];
    const float* wt   = (const float*)d_in[6];
    const float* lw   = (const float*)d_in[7];
    const float* bias = (const float*)d_in[8];
    float* out = (float*)d_out;

    const int M = in_sizes[5] / H;
    const int E = in_sizes[1];

    transpose512<<<dim3(16, 16), dim3(32, 8)>>>(lw);

    cudaMemsetAsync(d_out, 0, (size_t)out_size * sizeof(float));

    const int GB = ((M + 127) / 128) * 4;       // gemm blocks (128x128 tiles)
    const int EB = (E + EPB - 1) / EPB;         // edge blocks
    fused_kernel<<<GB + EB, 256>>>(emb, bias, d_in[1], d_in[2], d_in[3],
                                   norm, wt, out, M, E, GB);
}